// round 7
// baseline (speedup 1.0000x reference)
#include <cuda_runtime.h>
#include <cstdint>

#define NT 64
#define C 256
#define HW 3136
#define BM 128
#define BN 128
#define BK 32
#define KTILES 8

#define NTHREADS 384          // 8 consumer warps + 4 producer warps
#define STAGES 4
#define WSTRIDE 36
#define YSTRIDE 136
#define WBYTES (128 * WSTRIDE * 4)       // 18432
#define YBYTES (BK * YSTRIDE * 4)        // 17408
#define STAGEB (WBYTES + YBYTES)         // 35840
#define SM_BUF0 128                      // barriers live in [0,128)
#define SMEM_BYTES (SM_BUF0 + STAGES * STAGEB)   // 143488

__device__ __forceinline__ unsigned f2tf32(float f) {
    unsigned r;
    asm("cvt.rna.tf32.f32 %0, %1;" : "=r"(r) : "f"(f));
    return r;
}
__device__ __forceinline__ unsigned smem_u32(const void* p) {
    return (unsigned)__cvta_generic_to_shared(p);
}
__device__ __forceinline__ void cp_async16(unsigned dst, const void* src) {
    asm volatile("cp.async.ca.shared.global [%0], [%1], 16;\n" :: "r"(dst), "l"(src));
}
__device__ __forceinline__ void mbar_init(unsigned a, unsigned cnt) {
    asm volatile("mbarrier.init.shared.b64 [%0], %1;" :: "r"(a), "r"(cnt) : "memory");
}
__device__ __forceinline__ void mbar_arrive(unsigned a) {
    asm volatile("mbarrier.arrive.shared.b64 _, [%0];" :: "r"(a) : "memory");
}
__device__ __forceinline__ void mbar_wait(unsigned a, unsigned parity) {
    unsigned done;
    asm volatile(
        "{\n\t.reg .pred p;\n\t"
        "mbarrier.try_wait.parity.acquire.cta.shared::cta.b64 p, [%1], %2;\n\t"
        "selp.b32 %0, 1, 0, p;\n\t}"
        : "=r"(done) : "r"(a), "r"(parity) : "memory");
    if (!done) {
        asm volatile(
            "{\n\t.reg .pred P1;\n\t"
            "WL_%=:\n\t"
            "mbarrier.try_wait.parity.acquire.cta.shared::cta.b64 P1, [%0], %1, 0x989680;\n\t"
            "@P1 bra.uni WD_%=;\n\t"
            "bra.uni WL_%=;\n\t"
            "WD_%=:\n\t}"
            :: "r"(a), "r"(parity) : "memory");
    }
}

__global__ __launch_bounds__(NTHREADS, 1)
void msconv_ws_kernel(const float* __restrict__ x,
                      const float* __restrict__ net_w,
                      float* __restrict__ out) {
    extern __shared__ __align__(128) char smem[];
    const unsigned sb = smem_u32(smem);

    const int tid  = threadIdx.x;
    const int lane = tid & 31;
    const int wid  = tid >> 5;
    const int hw0  = blockIdx.x * BN;
    const int m0   = blockIdx.y * BM;
    const int z    = blockIdx.z;
    const int t    = z & 7;

    // barrier addresses: full[s] = 16s, empty[s] = 16s+8
    if (tid == 0) {
#pragma unroll
        for (int s = 0; s < STAGES; ++s) {
            mbar_init(sb + 16 * s, 128);       // full: producer threads
            mbar_init(sb + 16 * s + 8, 256);   // empty: consumer threads
        }
    }
    __syncthreads();

    if (wid >= 8) {
        // =============== PRODUCER (warps 8-11, 128 threads) ===============
        const int ptid = tid - 256;           // 0..127
        const int pw   = ptid >> 5;           // 0..3
        const int hw   = hw0 + lane * 4;
        const bool ok  = hw < HW;

        for (int kt = 0; kt < KTILES; ++kt) {
            const int stage = kt & (STAGES - 1);
            const unsigned fullb  = sb + 16 * stage;
            const unsigned emptyb = sb + 16 * stage + 8;
            const unsigned wOff = SM_BUF0 + stage * STAGEB;
            const unsigned yOff = wOff + WBYTES;

            // wait until consumers released this stage (first pass: immediate)
            mbar_wait(emptyb, (kt >> 2) ^ 1);

            // W tile: thread owns one row, 8 x cp.async 16B
            {
                const float* src = net_w + (size_t)(m0 + ptid) * C + kt * BK;
                unsigned dst = sb + wOff + ptid * (WSTRIDE * 4);
#pragma unroll
                for (int j = 0; j < 8; ++j)
                    cp_async16(dst + j * 16, src + j * 4);
                asm volatile("cp.async.commit_group;\n" ::: "memory");
            }

            // Y tile: fused temporal shift-sum; warp owns 8 channel rows
#pragma unroll
            for (int p = 0; p < 8; ++p) {
                int kl = pw * 8 + p;
                int ci = kt * BK + kl;
                int g  = ci >> 6;
                int cg = ci & 63;
                int lo, hi;
                if (g == 0 || cg >= 32) { lo = 0;  hi = 0;  }
                else if (cg < 16)       { lo = -g; hi = -1; }
                else                    { lo = 1;  hi = g;  }
                float4 a = make_float4(0.f, 0.f, 0.f, 0.f);
                if (ok) {
                    for (int dt = lo; dt <= hi; ++dt) {
                        int tt = t + dt;
                        if ((unsigned)tt < 8u) {
                            const float4 xv = *reinterpret_cast<const float4*>(
                                x + ((size_t)(z + dt) * C + ci) * HW + hw);
                            a.x += xv.x; a.y += xv.y; a.z += xv.z; a.w += xv.w;
                        }
                    }
                }
                uint4 s;
                s.x = f2tf32(a.x); s.y = f2tf32(a.y);
                s.z = f2tf32(a.z); s.w = f2tf32(a.w);
                *reinterpret_cast<uint4*>(
                    smem + yOff + (kl * YSTRIDE + lane * 4) * 4) = s;
            }

            asm volatile("cp.async.wait_group 0;\n" ::: "memory");
            mbar_arrive(fullb);   // release: W + Y visible to consumers
        }
        return;   // producers exit; smem stays valid
    }

    // =============== CONSUMER (warps 0-7, 256 threads) ===============
    const int wm = (wid >> 2) * 64;
    const int wn = (wid & 3) * 32;
    const int ar = lane >> 2;
    const int ac = lane & 3;

    float acc[4][4][4];
#pragma unroll
    for (int i = 0; i < 4; ++i)
#pragma unroll
        for (int j = 0; j < 4; ++j)
#pragma unroll
            for (int k = 0; k < 4; ++k) acc[i][j][k] = 0.f;

    for (int kt = 0; kt < KTILES; ++kt) {
        const int stage = kt & (STAGES - 1);
        const unsigned fullb  = sb + 16 * stage;
        const unsigned emptyb = sb + 16 * stage + 8;
        const unsigned* Ws = reinterpret_cast<const unsigned*>(
            smem + SM_BUF0 + stage * STAGEB);
        const unsigned* Ys = reinterpret_cast<const unsigned*>(
            smem + SM_BUF0 + stage * STAGEB + WBYTES);

        mbar_wait(fullb, kt >> 2);   // acquire

#pragma unroll
        for (int kk = 0; kk < 4; ++kk) {
            int k0 = kk * 8;
            unsigned a[4][4], b[4][2];
#pragma unroll
            for (int mi = 0; mi < 4; ++mi) {
                int m = wm + mi * 16;
                a[mi][0] = Ws[(m + ar    ) * WSTRIDE + k0 + ac    ];
                a[mi][1] = Ws[(m + ar + 8) * WSTRIDE + k0 + ac    ];
                a[mi][2] = Ws[(m + ar    ) * WSTRIDE + k0 + ac + 4];
                a[mi][3] = Ws[(m + ar + 8) * WSTRIDE + k0 + ac + 4];
            }
#pragma unroll
            for (int ni = 0; ni < 4; ++ni) {
                int nn = wn + ni * 8 + ar;
                b[ni][0] = Ys[(k0 + ac    ) * YSTRIDE + nn];
                b[ni][1] = Ys[(k0 + ac + 4) * YSTRIDE + nn];
            }
#pragma unroll
            for (int mi = 0; mi < 4; ++mi)
#pragma unroll
                for (int ni = 0; ni < 4; ++ni) {
                    asm volatile(
                        "mma.sync.aligned.m16n8k8.row.col.f32.tf32.tf32.f32 "
                        "{%0,%1,%2,%3}, {%4,%5,%6,%7}, {%8,%9}, {%0,%1,%2,%3};\n"
                        : "+f"(acc[mi][ni][0]), "+f"(acc[mi][ni][1]),
                          "+f"(acc[mi][ni][2]), "+f"(acc[mi][ni][3])
                        : "r"(a[mi][0]), "r"(a[mi][1]),
                          "r"(a[mi][2]), "r"(a[mi][3]),
                          "r"(b[ni][0]), "r"(b[ni][1]));
                }
        }

        mbar_arrive(emptyb);   // stage free for producers
    }

    // ---- epilogue: direct register -> gmem ----
    const int r  = lane >> 2;
    const int c2 = (lane & 3) * 2;
#pragma unroll
    for (int mi = 0; mi < 4; ++mi) {
#pragma unroll
        for (int ni = 0; ni < 4; ++ni) {
            int co  = m0 + wm + mi * 16 + r;
            int hwo = hw0 + wn + ni * 8 + c2;
            if (hwo < HW) {
                float2 v0 = make_float2(acc[mi][ni][0], acc[mi][ni][1]);
                float2 v1 = make_float2(acc[mi][ni][2], acc[mi][ni][3]);
                *reinterpret_cast<float2*>(
                    out + ((size_t)z * C + co) * HW + hwo) = v0;
                *reinterpret_cast<float2*>(
                    out + ((size_t)z * C + co + 8) * HW + hwo) = v1;
            }
        }
    }
}

extern "C" void kernel_launch(void* const* d_in, const int* in_sizes, int n_in,
                              void* d_out, int out_size) {
    const float* x     = (const float*)d_in[0];
    const float* net_w = (const float*)d_in[5];
    float* out = (float*)d_out;

    static bool attr_done = false;
    if (!attr_done) {
        cudaFuncSetAttribute(msconv_ws_kernel,
                             cudaFuncAttributeMaxDynamicSharedMemorySize,
                             SMEM_BYTES);
        attr_done = true;
    }

    dim3 grid((HW + BN - 1) / BN, C / BM, NT);   // 25 x 2 x 64
    msconv_ws_kernel<<<grid, NTHREADS, SMEM_BYTES>>>(x, net_w, out);
}

// round 8
// speedup vs baseline: 2.9169x; 2.9169x over previous
#include <cuda_runtime.h>
#include <cstdint>

#define NT 64
#define C 256
#define HW 3136
#define BM 128
#define BN 96
#define BK 32
#define KTILES 8

#define NTHREADS 384
#define WSTRIDE 36
#define YSTRIDE 104
#define WBYTES (128 * WSTRIDE * 4)        // 18432
#define YBYTES (BK * YSTRIDE * 4)         // 13312
#define STAGEB (WBYTES + YBYTES)          // 31744
#define SMEM_BYTES (2 * STAGEB)           // 63488

#define NJOBS (BK * (BN / 4))             // 768 float4 jobs per Y tile

__device__ __forceinline__ unsigned f2tf32(float f) {
    unsigned r;
    asm("cvt.rna.tf32.f32 %0, %1;" : "=r"(r) : "f"(f));
    return r;
}
__device__ __forceinline__ unsigned smem_u32(const void* p) {
    return (unsigned)__cvta_generic_to_shared(p);
}
__device__ __forceinline__ void cp_async16(unsigned dst, const void* src) {
    asm volatile("cp.async.ca.shared.global [%0], [%1], 16;\n" :: "r"(dst), "l"(src));
}

__global__ __launch_bounds__(NTHREADS, 2)
void msconv_kernel(const float* __restrict__ x,
                   const float* __restrict__ net_w,
                   float* __restrict__ out) {
    extern __shared__ __align__(128) char smem[];
    const unsigned sb = smem_u32(smem);

    const int tid  = threadIdx.x;
    const int lane = tid & 31;
    const int wid  = tid >> 5;          // 0..11
    const int hw0  = blockIdx.x * BN;
    const int m0   = blockIdx.y * BM;
    const int z    = blockIdx.z;
    const int t    = z & 7;

    // consumer warp layout: 2 (m) x 6 (n); warp tile 64 x 16
    const int wm = (wid / 6) * 64;
    const int wn = (wid % 6) * 16;
    const int ar = lane >> 2;
    const int ac = lane & 3;

    // producer job constants (2 jobs per thread)
    const int kl0   = tid / (BN / 4);          // job A: k-row
    const int col0  = tid % (BN / 4);          // job A: float4 col
    const int kl1   = (tid + NTHREADS) / (BN / 4);
    const int col1  = (tid + NTHREADS) % (BN / 4);
    const int hwA   = hw0 + col0 * 4;
    const int hwB   = hw0 + col1 * 4;
    const bool okA  = hwA < HW;
    const bool okB  = hwB < HW;

    float acc[4][2][4];
#pragma unroll
    for (int i = 0; i < 4; ++i)
#pragma unroll
        for (int j = 0; j < 2; ++j)
#pragma unroll
            for (int k = 0; k < 4; ++k) acc[i][j][k] = 0.f;

    auto issueW = [&](int kt, unsigned wOff) {
#pragma unroll
        for (int j = 0; j < 3; ++j) {
            int cidx = tid + NTHREADS * j;      // 16B chunk id, 1024 total
            if (cidx < 1024) {
                int row  = cidx >> 3;
                int colf = (cidx & 7) * 4;
                cp_async16(sb + wOff + (row * WSTRIDE + colf) * 4,
                           net_w + (size_t)(m0 + row) * C + kt * BK + colf);
            }
        }
        asm volatile("cp.async.commit_group;\n" ::: "memory");
    };

    auto shiftSum = [&](int kt, int kl, int hw, bool ok) -> float4 {
        int ci = kt * BK + kl;
        int g  = ci >> 6;
        int cg = ci & 63;
        int lo, hi;
        if (g == 0 || cg >= 32) { lo = 0;  hi = 0;  }
        else if (cg < 16)       { lo = -g; hi = -1; }
        else                    { lo = 1;  hi = g;  }
        float4 a = make_float4(0.f, 0.f, 0.f, 0.f);
        if (ok) {
            for (int dt = lo; dt <= hi; ++dt) {
                int tt = t + dt;
                if ((unsigned)tt < 8u) {
                    const float4 xv = *reinterpret_cast<const float4*>(
                        x + ((size_t)(z + dt) * C + ci) * HW + hw);
                    a.x += xv.x; a.y += xv.y; a.z += xv.z; a.w += xv.w;
                }
            }
        }
        return a;
    };

    auto storeY = [&](unsigned yOff, const float4& vA, const float4& vB) {
        uint4 s;
        s.x = f2tf32(vA.x); s.y = f2tf32(vA.y);
        s.z = f2tf32(vA.z); s.w = f2tf32(vA.w);
        *reinterpret_cast<uint4*>(smem + yOff + (kl0 * YSTRIDE + col0 * 4) * 4) = s;
        s.x = f2tf32(vB.x); s.y = f2tf32(vB.y);
        s.z = f2tf32(vB.z); s.w = f2tf32(vB.w);
        *reinterpret_cast<uint4*>(smem + yOff + (kl1 * YSTRIDE + col1 * 4) * 4) = s;
    };

    // ---- prologue: fill buffer 0 ----
    {
        issueW(0, 0);
        float4 a = shiftSum(0, kl0, hwA, okA);
        float4 b = shiftSum(0, kl1, hwB, okB);
        storeY(WBYTES, a, b);
        asm volatile("cp.async.wait_group 0;\n" ::: "memory");
        __syncthreads();
    }

    float4 yA, yB;
    for (int kt = 0; kt < KTILES; ++kt) {
        const int cur = kt & 1;
        const unsigned wCur = cur ? STAGEB : 0;
        const unsigned yCur = wCur + WBYTES;
        const unsigned wNxt = cur ? 0 : STAGEB;
        const unsigned yNxt = wNxt + WBYTES;

        if (kt < KTILES - 1) {
            issueW(kt + 1, wNxt);
            yA = shiftSum(kt + 1, kl0, hwA, okA);
            yB = shiftSum(kt + 1, kl1, hwB, okB);
        }

        const unsigned* Ws = reinterpret_cast<const unsigned*>(smem + wCur);
        const unsigned* Ys = reinterpret_cast<const unsigned*>(smem + yCur);
#pragma unroll
        for (int kk = 0; kk < 4; ++kk) {
            int k0 = kk * 8;
            unsigned a[4][4], b[2][2];
#pragma unroll
            for (int mi = 0; mi < 4; ++mi) {
                int m = wm + mi * 16;
                a[mi][0] = Ws[(m + ar    ) * WSTRIDE + k0 + ac    ];
                a[mi][1] = Ws[(m + ar + 8) * WSTRIDE + k0 + ac    ];
                a[mi][2] = Ws[(m + ar    ) * WSTRIDE + k0 + ac + 4];
                a[mi][3] = Ws[(m + ar + 8) * WSTRIDE + k0 + ac + 4];
            }
#pragma unroll
            for (int ni = 0; ni < 2; ++ni) {
                int nn = wn + ni * 8 + ar;
                b[ni][0] = Ys[(k0 + ac    ) * YSTRIDE + nn];
                b[ni][1] = Ys[(k0 + ac + 4) * YSTRIDE + nn];
            }
#pragma unroll
            for (int mi = 0; mi < 4; ++mi)
#pragma unroll
                for (int ni = 0; ni < 2; ++ni) {
                    asm volatile(
                        "mma.sync.aligned.m16n8k8.row.col.f32.tf32.tf32.f32 "
                        "{%0,%1,%2,%3}, {%4,%5,%6,%7}, {%8,%9}, {%0,%1,%2,%3};\n"
                        : "+f"(acc[mi][ni][0]), "+f"(acc[mi][ni][1]),
                          "+f"(acc[mi][ni][2]), "+f"(acc[mi][ni][3])
                        : "r"(a[mi][0]), "r"(a[mi][1]),
                          "r"(a[mi][2]), "r"(a[mi][3]),
                          "r"(b[ni][0]), "r"(b[ni][1]));
                }
        }

        if (kt < KTILES - 1) {
            storeY(yNxt, yA, yB);
            asm volatile("cp.async.wait_group 0;\n" ::: "memory");
            __syncthreads();
        }
    }

    // ---- epilogue ----
    const int r  = lane >> 2;
    const int c2 = (lane & 3) * 2;
#pragma unroll
    for (int mi = 0; mi < 4; ++mi) {
#pragma unroll
        for (int ni = 0; ni < 2; ++ni) {
            int co  = m0 + wm + mi * 16 + r;
            int hwo = hw0 + wn + ni * 8 + c2;
            if (hwo < HW) {
                float2 v0 = make_float2(acc[mi][ni][0], acc[mi][ni][1]);
                float2 v1 = make_float2(acc[mi][ni][2], acc[mi][ni][3]);
                *reinterpret_cast<float2*>(
                    out + ((size_t)z * C + co) * HW + hwo) = v0;
                *reinterpret_cast<float2*>(
                    out + ((size_t)z * C + co + 8) * HW + hwo) = v1;
            }
        }
    }
}

extern "C" void kernel_launch(void* const* d_in, const int* in_sizes, int n_in,
                              void* d_out, int out_size) {
    const float* x     = (const float*)d_in[0];
    const float* net_w = (const float*)d_in[5];
    float* out = (float*)d_out;

    static bool attr_done = false;
    if (!attr_done) {
        cudaFuncSetAttribute(msconv_kernel,
                             cudaFuncAttributeMaxDynamicSharedMemorySize,
                             SMEM_BYTES);
        attr_done = true;
    }

    dim3 grid((HW + BN - 1) / BN, C / BM, NT);   // 33 x 2 x 64
    msconv_kernel<<<grid, NTHREADS, SMEM_BYTES>>>(x, net_w, out);
}

// round 10
// speedup vs baseline: 3.5669x; 1.2228x over previous
#include <cuda_runtime.h>
#include <cstdint>

#define NT 64
#define C 256
#define HW 3136
#define BM 256
#define BN 96
#define BK 32
#define KTILES 8

#define NTHREADS 768
#define WSTRIDE 36
#define YSTRIDE 104
#define WBYTES (BM * WSTRIDE * 4)         // 36864
#define YBYTES (BK * YSTRIDE * 4)         // 13312
#define STAGEB (WBYTES + YBYTES)          // 50176
#define SMEM_BYTES (2 * STAGEB)           // 100352

__device__ __forceinline__ unsigned f2tf32(float f) {
    unsigned r;
    asm("cvt.rna.tf32.f32 %0, %1;" : "=r"(r) : "f"(f));
    return r;
}
__device__ __forceinline__ unsigned smem_u32(const void* p) {
    return (unsigned)__cvta_generic_to_shared(p);
}
__device__ __forceinline__ void cp_async16(unsigned dst, const void* src) {
    asm volatile("cp.async.ca.shared.global [%0], [%1], 16;\n" :: "r"(dst), "l"(src));
}

__global__ __launch_bounds__(NTHREADS, 1)
void msconv_kernel(const float* __restrict__ x,
                   const float* __restrict__ net_w,
                   float* __restrict__ out) {
    extern __shared__ __align__(128) char smem[];
    const unsigned sb = smem_u32(smem);

    const int tid  = threadIdx.x;
    const int lane = tid & 31;
    const int wid  = tid >> 5;          // 0..23
    const int hw0  = blockIdx.x * BN;
    const int z    = blockIdx.y;
    const int t    = z & 7;

    // consumer warp layout: 8 (m) x 3 (n); warp tile 32 x 32
    const int wm = (wid / 3) * 32;
    const int wn = (wid % 3) * 32;
    const int ar = lane >> 2;
    const int ac = lane & 3;

    // producer: exactly 1 float4 job per thread (32 k-rows x 24 cols)
    const int kl  = tid / (BN / 4);     // 0..31
    const int col = tid % (BN / 4);     // 0..23
    const int hw  = hw0 + col * 4;
    const bool ok = hw < HW;

    float acc[2][4][4];
#pragma unroll
    for (int i = 0; i < 2; ++i)
#pragma unroll
        for (int j = 0; j < 4; ++j)
#pragma unroll
            for (int k = 0; k < 4; ++k) acc[i][j][k] = 0.f;

    auto issueW = [&](int kt, unsigned wOff) {
#pragma unroll
        for (int j = 0; j < 3; ++j) {
            int cidx = tid + NTHREADS * j;      // 16B chunk id, 2048 total
            if (cidx < 2048) {
                int row  = cidx >> 3;
                int colf = (cidx & 7) * 4;
                cp_async16(sb + wOff + (row * WSTRIDE + colf) * 4,
                           net_w + (size_t)row * C + kt * BK + colf);
            }
        }
        asm volatile("cp.async.commit_group;\n" ::: "memory");
    };

    auto shiftSum = [&](int kt) -> float4 {
        int ci = kt * BK + kl;
        int g  = ci >> 6;
        int cg = ci & 63;
        int lo, hi;
        if (g == 0 || cg >= 32) { lo = 0;  hi = 0;  }
        else if (cg < 16)       { lo = -g; hi = -1; }
        else                    { lo = 1;  hi = g;  }
        float4 a = make_float4(0.f, 0.f, 0.f, 0.f);
        if (ok) {
            for (int dt = lo; dt <= hi; ++dt) {
                int tt = t + dt;
                if ((unsigned)tt < 8u) {
                    const float4 xv = *reinterpret_cast<const float4*>(
                        x + ((size_t)(z + dt) * C + ci) * HW + hw);
                    a.x += xv.x; a.y += xv.y; a.z += xv.z; a.w += xv.w;
                }
            }
        }
        return a;
    };

    auto storeY = [&](unsigned yOff, const float4& v) {
        uint4 s;
        s.x = f2tf32(v.x); s.y = f2tf32(v.y);
        s.z = f2tf32(v.z); s.w = f2tf32(v.w);
        *reinterpret_cast<uint4*>(smem + yOff + (kl * YSTRIDE + col * 4) * 4) = s;
    };

    // ---- prologue: fill buffer 0 ----
    {
        issueW(0, 0);
        float4 v = shiftSum(0);
        storeY(WBYTES, v);
        asm volatile("cp.async.wait_group 0;\n" ::: "memory");
        __syncthreads();
    }

    float4 yv;
    for (int kt = 0; kt < KTILES; ++kt) {
        const int cur = kt & 1;
        const unsigned wCur = cur ? STAGEB : 0;
        const unsigned yCur = wCur + WBYTES;
        const unsigned wNxt = cur ? 0 : STAGEB;
        const unsigned yNxt = wNxt + WBYTES;

        if (kt < KTILES - 1) {
            issueW(kt + 1, wNxt);
            yv = shiftSum(kt + 1);
        }

        const unsigned* Ws = reinterpret_cast<const unsigned*>(smem + wCur);
        const unsigned* Ys = reinterpret_cast<const unsigned*>(smem + yCur);
#pragma unroll
        for (int kk = 0; kk < 4; ++kk) {
            int k0 = kk * 8;
            unsigned a[2][4], b[4][2];
#pragma unroll
            for (int mi = 0; mi < 2; ++mi) {
                int m = wm + mi * 16;
                a[mi][0] = Ws[(m + ar    ) * WSTRIDE + k0 + ac    ];
                a[mi][1] = Ws[(m + ar + 8) * WSTRIDE + k0 + ac    ];
                a[mi][2] = Ws[(m + ar    ) * WSTRIDE + k0 + ac + 4];
                a[mi][3] = Ws[(m + ar + 8) * WSTRIDE + k0 + ac + 4];
            }
#pragma unroll
            for (int ni = 0; ni < 4; ++ni) {
                int nn = wn + ni * 8 + ar;
                b[ni][0] = Ys[(k0 + ac    ) * YSTRIDE + nn];
                b[ni][1] = Ys[(k0 + ac + 4) * YSTRIDE + nn];
            }
#pragma unroll
            for (int mi = 0; mi < 2; ++mi)
#pragma unroll
                for (int ni = 0; ni < 4; ++ni) {
                    asm volatile(
                        "mma.sync.aligned.m16n8k8.row.col.f32.tf32.tf32.f32 "
                        "{%0,%1,%2,%3}, {%4,%5,%6,%7}, {%8,%9}, {%0,%1,%2,%3};\n"
                        : "+f"(acc[mi][ni][0]), "+f"(acc[mi][ni][1]),
                          "+f"(acc[mi][ni][2]), "+f"(acc[mi][ni][3])
                        : "r"(a[mi][0]), "r"(a[mi][1]),
                          "r"(a[mi][2]), "r"(a[mi][3]),
                          "r"(b[ni][0]), "r"(b[ni][1]));
                }
        }

        if (kt < KTILES - 1) {
            storeY(yNxt, yv);
            asm volatile("cp.async.wait_group 0;\n" ::: "memory");
            __syncthreads();
        }
    }

    // ---- epilogue ----
    const int r  = lane >> 2;
    const int c2 = (lane & 3) * 2;
#pragma unroll
    for (int mi = 0; mi < 2; ++mi) {
#pragma unroll
        for (int ni = 0; ni < 4; ++ni) {
            int co  = wm + mi * 16 + r;
            int hwo = hw0 + wn + ni * 8 + c2;
            if (hwo < HW) {
                float2 v0 = make_float2(acc[mi][ni][0], acc[mi][ni][1]);
                float2 v1 = make_float2(acc[mi][ni][2], acc[mi][ni][3]);
                *reinterpret_cast<float2*>(
                    out + ((size_t)z * C + co) * HW + hwo) = v0;
                *reinterpret_cast<float2*>(
                    out + ((size_t)z * C + co + 8) * HW + hwo) = v1;
            }
        }
    }
}

extern "C" void kernel_launch(void* const* d_in, const int* in_sizes, int n_in,
                              void* d_out, int out_size) {
    const float* x     = (const float*)d_in[0];
    const float* net_w = (const float*)d_in[5];
    float* out = (float*)d_out;

    static bool attr_done = false;
    if (!attr_done) {
        cudaFuncSetAttribute(msconv_kernel,
                             cudaFuncAttributeMaxDynamicSharedMemorySize,
                             SMEM_BYTES);
        attr_done = true;
    }

    dim3 grid((HW + BN - 1) / BN, NT);   // 33 x 64 = 2112 CTAs
    msconv_kernel<<<grid, NTHREADS, SMEM_BYTES>>>(x, net_w, out);
}

// round 11
// speedup vs baseline: 3.5947x; 1.0078x over previous
#include <cuda_runtime.h>
#include <cstdint>

#define NT 64
#define C 256
#define HW 3136
#define BM 256
#define BN 96
#define BK 32
#define KTILES 8

#define NTHREADS 768
#define WSTRIDE 36
#define YSTRIDE 104
#define WBYTES (BM * WSTRIDE * 4)         // 36864
#define YBYTES (BK * YSTRIDE * 4)         // 13312
#define STAGEB (WBYTES + YBYTES)          // 50176
#define SMEM_BYTES (2 * STAGEB)           // 100352

__device__ __forceinline__ unsigned f2tf32(float f) {
    unsigned r;
    asm("cvt.rna.tf32.f32 %0, %1;" : "=r"(r) : "f"(f));
    return r;
}
__device__ __forceinline__ unsigned smem_u32(const void* p) {
    return (unsigned)__cvta_generic_to_shared(p);
}
__device__ __forceinline__ void cp_async16(unsigned dst, const void* src) {
    asm volatile("cp.async.ca.shared.global [%0], [%1], 16;\n" :: "r"(dst), "l"(src));
}
__device__ __forceinline__ void prefetch_l2(const void* p) {
    asm volatile("prefetch.global.L2 [%0];" :: "l"(p));
}

__global__ __launch_bounds__(NTHREADS, 1)
void msconv_kernel(const float* __restrict__ x,
                   const float* __restrict__ net_w,
                   float* __restrict__ out) {
    extern __shared__ __align__(128) char smem[];
    const unsigned sb = smem_u32(smem);

    const int tid  = threadIdx.x;
    const int lane = tid & 31;
    const int wid  = tid >> 5;          // 0..23
    const int z    = blockIdx.x;        // z fastest -> launch-order neighbors share x frames in L2
    const int hw0  = blockIdx.y * BN;
    const int t    = z & 7;

    // consumer warp layout: 8 (m) x 3 (n); warp tile 32 x 32
    const int wm = (wid / 3) * 32;
    const int wn = (wid % 3) * 32;
    const int ar = lane >> 2;
    const int ac = lane & 3;

    // producer: exactly 1 float4 job per thread (32 k-rows x 24 cols)
    const int kl  = tid / (BN / 4);     // 0..31
    const int col = tid % (BN / 4);     // 0..23
    const int hw  = hw0 + col * 4;
    const bool ok = hw < HW;

    float acc[2][4][4];
#pragma unroll
    for (int i = 0; i < 2; ++i)
#pragma unroll
        for (int j = 0; j < 4; ++j)
#pragma unroll
            for (int k = 0; k < 4; ++k) acc[i][j][k] = 0.f;

    auto tapRange = [&](int kt, int& lo, int& hi) {
        int ci = kt * BK + kl;
        int g  = ci >> 6;
        int cg = ci & 63;
        if (g == 0 || cg >= 32) { lo = 0;  hi = 0;  }
        else if (cg < 16)       { lo = -g; hi = -1; }
        else                    { lo = 1;  hi = g;  }
    };

    auto issueW = [&](int kt, unsigned wOff) {
#pragma unroll
        for (int j = 0; j < 3; ++j) {
            int cidx = tid + NTHREADS * j;      // 16B chunk id, 2048 total
            if (cidx < 2048) {
                int row  = cidx >> 3;
                int colf = (cidx & 7) * 4;
                cp_async16(sb + wOff + (row * WSTRIDE + colf) * 4,
                           net_w + (size_t)row * C + kt * BK + colf);
            }
        }
        asm volatile("cp.async.commit_group;\n" ::: "memory");
    };

    auto shiftSum = [&](int kt) -> float4 {
        int lo, hi;
        tapRange(kt, lo, hi);
        int ci = kt * BK + kl;
        float4 a = make_float4(0.f, 0.f, 0.f, 0.f);
        if (ok) {
            for (int dt = lo; dt <= hi; ++dt) {
                int tt = t + dt;
                if ((unsigned)tt < 8u) {
                    const float4 xv = *reinterpret_cast<const float4*>(
                        x + ((size_t)(z + dt) * C + ci) * HW + hw);
                    a.x += xv.x; a.y += xv.y; a.z += xv.z; a.w += xv.w;
                }
            }
        }
        return a;
    };

    auto prefetchX = [&](int kt) {
        int lo, hi;
        tapRange(kt, lo, hi);
        int ci = kt * BK + kl;
        if (ok) {
            for (int dt = lo; dt <= hi; ++dt) {
                int tt = t + dt;
                if ((unsigned)tt < 8u)
                    prefetch_l2(x + ((size_t)(z + dt) * C + ci) * HW + hw);
            }
        }
    };

    auto storeY = [&](unsigned yOff, const float4& v) {
        uint4 s;
        s.x = f2tf32(v.x); s.y = f2tf32(v.y);
        s.z = f2tf32(v.z); s.w = f2tf32(v.w);
        *reinterpret_cast<uint4*>(smem + yOff + (kl * YSTRIDE + col * 4) * 4) = s;
    };

    // ---- prologue: fill buffer 0 (prefetch tile 1 while tile 0 stalls) ----
    {
        issueW(0, 0);
        prefetchX(1);
        float4 v = shiftSum(0);
        storeY(WBYTES, v);
        asm volatile("cp.async.wait_group 0;\n" ::: "memory");
        __syncthreads();
    }

    float4 yv;
    for (int kt = 0; kt < KTILES; ++kt) {
        const int cur = kt & 1;
        const unsigned wCur = cur ? STAGEB : 0;
        const unsigned yCur = wCur + WBYTES;
        const unsigned wNxt = cur ? 0 : STAGEB;
        const unsigned yNxt = wNxt + WBYTES;

        if (kt < KTILES - 1) {
            issueW(kt + 1, wNxt);
            yv = shiftSum(kt + 1);      // loads should hit L2 (prefetched last iter)
        }
        if (kt < KTILES - 2)
            prefetchX(kt + 2);          // warm L2 two tiles ahead

        const unsigned* Ws = reinterpret_cast<const unsigned*>(smem + wCur);
        const unsigned* Ys = reinterpret_cast<const unsigned*>(smem + yCur);
#pragma unroll
        for (int kk = 0; kk < 4; ++kk) {
            int k0 = kk * 8;
            unsigned a[2][4], b[4][2];
#pragma unroll
            for (int mi = 0; mi < 2; ++mi) {
                int m = wm + mi * 16;
                a[mi][0] = Ws[(m + ar    ) * WSTRIDE + k0 + ac    ];
                a[mi][1] = Ws[(m + ar + 8) * WSTRIDE + k0 + ac    ];
                a[mi][2] = Ws[(m + ar    ) * WSTRIDE + k0 + ac + 4];
                a[mi][3] = Ws[(m + ar + 8) * WSTRIDE + k0 + ac + 4];
            }
#pragma unroll
            for (int ni = 0; ni < 4; ++ni) {
                int nn = wn + ni * 8 + ar;
                b[ni][0] = Ys[(k0 + ac    ) * YSTRIDE + nn];
                b[ni][1] = Ys[(k0 + ac + 4) * YSTRIDE + nn];
            }
#pragma unroll
            for (int mi = 0; mi < 2; ++mi)
#pragma unroll
                for (int ni = 0; ni < 4; ++ni) {
                    asm volatile(
                        "mma.sync.aligned.m16n8k8.row.col.f32.tf32.tf32.f32 "
                        "{%0,%1,%2,%3}, {%4,%5,%6,%7}, {%8,%9}, {%0,%1,%2,%3};\n"
                        : "+f"(acc[mi][ni][0]), "+f"(acc[mi][ni][1]),
                          "+f"(acc[mi][ni][2]), "+f"(acc[mi][ni][3])
                        : "r"(a[mi][0]), "r"(a[mi][1]),
                          "r"(a[mi][2]), "r"(a[mi][3]),
                          "r"(b[ni][0]), "r"(b[ni][1]));
                }
        }

        if (kt < KTILES - 1) {
            storeY(yNxt, yv);
            asm volatile("cp.async.wait_group 0;\n" ::: "memory");
            __syncthreads();
        }
    }

    // ---- epilogue ----
    const int r  = lane >> 2;
    const int c2 = (lane & 3) * 2;
#pragma unroll
    for (int mi = 0; mi < 2; ++mi) {
#pragma unroll
        for (int ni = 0; ni < 4; ++ni) {
            int co  = wm + mi * 16 + r;
            int hwo = hw0 + wn + ni * 8 + c2;
            if (hwo < HW) {
                float2 v0 = make_float2(acc[mi][ni][0], acc[mi][ni][1]);
                float2 v1 = make_float2(acc[mi][ni][2], acc[mi][ni][3]);
                *reinterpret_cast<float2*>(
                    out + ((size_t)z * C + co) * HW + hwo) = v0;
                *reinterpret_cast<float2*>(
                    out + ((size_t)z * C + co + 8) * HW + hwo) = v1;
            }
        }
    }
}

extern "C" void kernel_launch(void* const* d_in, const int* in_sizes, int n_in,
                              void* d_out, int out_size) {
    const float* x     = (const float*)d_in[0];
    const float* net_w = (const float*)d_in[5];
    float* out = (float*)d_out;

    static bool attr_done = false;
    if (!attr_done) {
        cudaFuncSetAttribute(msconv_kernel,
                             cudaFuncAttributeMaxDynamicSharedMemorySize,
                             SMEM_BYTES);
        attr_done = true;
    }

    dim3 grid(NT, (HW + BN - 1) / BN);   // 64 x 33 = 2112 CTAs, z fastest
    msconv_kernel<<<grid, NTHREADS, SMEM_BYTES>>>(x, net_w, out);
}

// round 14
// speedup vs baseline: 3.9631x; 1.1025x over previous
#include <cuda_runtime.h>
#include <cstdint>

#define NT 64
#define C 256
#define HW 3136
#define BM 256
#define BN 96
#define BK 32
#define KTILES 8

#define NTHREADS 768
#define WSTRIDE 36
#define YSTRIDE 104
#define WBYTES (BM * WSTRIDE * 4)         // 36864
#define YBYTES (BK * YSTRIDE * 4)         // 13312
#define STAGEB (WBYTES + YBYTES)          // 50176
#define SMEM_BYTES (2 * STAGEB)           // 100352

__device__ __forceinline__ unsigned f2tf32(float f) {
    unsigned r;
    asm("cvt.rna.tf32.f32 %0, %1;" : "=r"(r) : "f"(f));
    return r;
}
__device__ __forceinline__ unsigned smem_u32(const void* p) {
    return (unsigned)__cvta_generic_to_shared(p);
}
__device__ __forceinline__ void cp_async16(unsigned dst, const void* src) {
    asm volatile("cp.async.ca.shared.global [%0], [%1], 16;\n" :: "r"(dst), "l"(src));
}

__global__ __launch_bounds__(NTHREADS, 1)
void msconv_kernel(const float* __restrict__ x,
                   const float* __restrict__ net_w,
                   float* __restrict__ out) {
    extern __shared__ __align__(128) char smem[];
    const unsigned sb = smem_u32(smem);

    const int tid  = threadIdx.x;
    const int lane = tid & 31;
    const int wid  = tid >> 5;          // 0..23
    const int z    = blockIdx.x;        // z fastest: launch-order neighbors share x frames in L2
    const int hw0  = blockIdx.y * BN;
    const int t    = z & 7;

    // consumer warp layout: 8 (m) x 3 (n); warp tile 32 x 32
    const int wm = (wid / 3) * 32;
    const int wn = (wid % 3) * 32;
    const int ar = lane >> 2;
    const int ac = lane & 3;

    // producer: exactly 1 float4 job per thread (32 k-rows x 24 cols)
    const int kl  = tid / (BN / 4);     // 0..31
    const int col = tid % (BN / 4);     // 0..23
    const int hw  = hw0 + col * 4;
    const bool ok = hw < HW;

    float acc[2][4][4];
#pragma unroll
    for (int i = 0; i < 2; ++i)
#pragma unroll
        for (int j = 0; j < 4; ++j)
#pragma unroll
            for (int k = 0; k < 4; ++k) acc[i][j][k] = 0.f;

    auto tapRange = [&](int kt, int& lo, int& hi) {
        int ci = kt * BK + kl;
        int g  = ci >> 6;
        int cg = ci & 63;
        if (g == 0 || cg >= 32) { lo = 0;  hi = 0;  }
        else if (cg < 16)       { lo = -g; hi = -1; }
        else                    { lo = 1;  hi = g;  }
    };

    auto issueW = [&](int kt, unsigned wOff) {
#pragma unroll
        for (int j = 0; j < 3; ++j) {
            int cidx = tid + NTHREADS * j;      // 16B chunk id, 2048 total
            if (cidx < 2048) {
                int row  = cidx >> 3;
                int colf = (cidx & 7) * 4;
                cp_async16(sb + wOff + (row * WSTRIDE + colf) * 4,
                           net_w + (size_t)row * C + kt * BK + colf);
            }
        }
        asm volatile("cp.async.commit_group;\n" ::: "memory");
    };

    // issue raw tap loads for tile kt into register buffer (no adds yet)
    auto issueY = [&](int kt, float4 xv[3]) {
        int lo, hi;
        tapRange(kt, lo, hi);
        int ci = kt * BK + kl;
        int ntap = hi - lo + 1;
#pragma unroll
        for (int i = 0; i < 3; ++i) {
            xv[i] = make_float4(0.f, 0.f, 0.f, 0.f);
            if (i < ntap) {
                int dt = lo + i;
                int tt = t + dt;
                if (ok && (unsigned)tt < 8u)
                    xv[i] = *reinterpret_cast<const float4*>(
                        x + ((size_t)(z + dt) * C + ci) * HW + hw);
            }
        }
    };

    // combine taps, cvt, store (runs AFTER the MMA block)
    auto finishY = [&](unsigned yOff, const float4 xv[3]) {
        float4 v;
        v.x = xv[0].x + xv[1].x + xv[2].x;
        v.y = xv[0].y + xv[1].y + xv[2].y;
        v.z = xv[0].z + xv[1].z + xv[2].z;
        v.w = xv[0].w + xv[1].w + xv[2].w;
        uint4 s;
        s.x = f2tf32(v.x); s.y = f2tf32(v.y);
        s.z = f2tf32(v.z); s.w = f2tf32(v.w);
        *reinterpret_cast<uint4*>(smem + yOff + (kl * YSTRIDE + col * 4) * 4) = s;
    };

    // ---- prologue: fill buffer 0 ----
    {
        float4 xv[3];
        issueW(0, 0);
        issueY(0, xv);
        finishY(WBYTES, xv);
        asm volatile("cp.async.wait_group 0;\n" ::: "memory");
        __syncthreads();
    }

    float4 xv[3];
    for (int kt = 0; kt < KTILES; ++kt) {
        const int cur = kt & 1;
        const unsigned wCur = cur ? STAGEB : 0;
        const unsigned yCur = wCur + WBYTES;
        const unsigned wNxt = cur ? 0 : STAGEB;
        const unsigned yNxt = wNxt + WBYTES;

        if (kt < KTILES - 1) {
            issueW(kt + 1, wNxt);       // async into next W buffer
            issueY(kt + 1, xv);         // raw LDGs in flight across the MMA block
        }

        const unsigned* Ws = reinterpret_cast<const unsigned*>(smem + wCur);
        const unsigned* Ys = reinterpret_cast<const unsigned*>(smem + yCur);
#pragma unroll
        for (int kk = 0; kk < 4; ++kk) {
            int k0 = kk * 8;
            unsigned a[2][4], b[4][2];
#pragma unroll
            for (int mi = 0; mi < 2; ++mi) {
                int m = wm + mi * 16;
                a[mi][0] = Ws[(m + ar    ) * WSTRIDE + k0 + ac    ];
                a[mi][1] = Ws[(m + ar + 8) * WSTRIDE + k0 + ac    ];
                a[mi][2] = Ws[(m + ar    ) * WSTRIDE + k0 + ac + 4];
                a[mi][3] = Ws[(m + ar + 8) * WSTRIDE + k0 + ac + 4];
            }
#pragma unroll
            for (int ni = 0; ni < 4; ++ni) {
                int nn = wn + ni * 8 + ar;
                b[ni][0] = Ys[(k0 + ac    ) * YSTRIDE + nn];
                b[ni][1] = Ys[(k0 + ac + 4) * YSTRIDE + nn];
            }
#pragma unroll
            for (int mi = 0; mi < 2; ++mi)
#pragma unroll
                for (int ni = 0; ni < 4; ++ni) {
                    asm volatile(
                        "mma.sync.aligned.m16n8k8.row.col.f32.tf32.tf32.f32 "
                        "{%0,%1,%2,%3}, {%4,%5,%6,%7}, {%8,%9}, {%0,%1,%2,%3};\n"
                        : "+f"(acc[mi][ni][0]), "+f"(acc[mi][ni][1]),
                          "+f"(acc[mi][ni][2]), "+f"(acc[mi][ni][3])
                        : "r"(a[mi][0]), "r"(a[mi][1]),
                          "r"(a[mi][2]), "r"(a[mi][3]),
                          "r"(b[ni][0]), "r"(b[ni][1]));
                }
        }

        if (kt < KTILES - 1) {
            finishY(yNxt, xv);          // loads have landed during the MMA block
            asm volatile("cp.async.wait_group 0;\n" ::: "memory");
            __syncthreads();
        }
    }

    // ---- epilogue ----
    const int r  = lane >> 2;
    const int c2 = (lane & 3) * 2;
#pragma unroll
    for (int mi = 0; mi < 2; ++mi) {
#pragma unroll
        for (int ni = 0; ni < 4; ++ni) {
            int co  = wm + mi * 16 + r;
            int hwo = hw0 + wn + ni * 8 + c2;
            if (hwo < HW) {
                float2 v0 = make_float2(acc[mi][ni][0], acc[mi][ni][1]);
                float2 v1 = make_float2(acc[mi][ni][2], acc[mi][ni][3]);
                *reinterpret_cast<float2*>(
                    out + ((size_t)z * C + co) * HW + hwo) = v0;
                *reinterpret_cast<float2*>(
                    out + ((size_t)z * C + co + 8) * HW + hwo) = v1;
            }
        }
    }
}

extern "C" void kernel_launch(void* const* d_in, const int* in_sizes, int n_in,
                              void* d_out, int out_size) {
    const float* x     = (const float*)d_in[0];
    const float* net_w = (const float*)d_in[5];
    float* out = (float*)d_out;

    static bool attr_done = false;
    if (!attr_done) {
        cudaFuncSetAttribute(msconv_kernel,
                             cudaFuncAttributeMaxDynamicSharedMemorySize,
                             SMEM_BYTES);
        attr_done = true;
    }

    dim3 grid(NT, (HW + BN - 1) / BN);   // 64 x 33 = 2112 CTAs, z fastest
    msconv_kernel<<<grid, NTHREADS, SMEM_BYTES>>>(x, net_w, out);
}

// round 15
// speedup vs baseline: 4.4392x; 1.1201x over previous
#include <cuda_runtime.h>
#include <cstdint>

#define NT 64
#define C 256
#define HW 3136
#define BM 256
#define BN 128
#define BK 32
#define KTILES 8

#define NTHREADS 512
#define WSTRIDE 36
#define YSTRIDE 136
#define WBYTES (BM * WSTRIDE * 4)         // 36864
#define YBYTES (BK * YSTRIDE * 4)         // 17408
#define STAGEB (WBYTES + YBYTES)          // 54272
#define SMEM_BYTES (2 * STAGEB)           // 108544

__device__ __forceinline__ unsigned f2tf32(float f) {
    unsigned r;
    asm("cvt.rna.tf32.f32 %0, %1;" : "=r"(r) : "f"(f));
    return r;
}
__device__ __forceinline__ unsigned smem_u32(const void* p) {
    return (unsigned)__cvta_generic_to_shared(p);
}
__device__ __forceinline__ void cp_async16(unsigned dst, const void* src) {
    asm volatile("cp.async.ca.shared.global [%0], [%1], 16;\n" :: "r"(dst), "l"(src));
}

__global__ __launch_bounds__(NTHREADS, 1)
void msconv_kernel(const float* __restrict__ x,
                   const float* __restrict__ net_w,
                   float* __restrict__ out) {
    extern __shared__ __align__(128) char smem[];
    const unsigned sb = smem_u32(smem);

    const int tid  = threadIdx.x;
    const int lane = tid & 31;
    const int wid  = tid >> 5;          // 0..15
    const int z    = blockIdx.x;        // z fastest: launch-order neighbors share x frames in L2
    const int hw0  = blockIdx.y * BN;
    const int t    = z & 7;

    // consumer warp layout: 4 (m) x 4 (n); warp tile 64 x 32
    const int wm = (wid >> 2) * 64;
    const int wn = (wid & 3) * 32;
    const int ar = lane >> 2;
    const int ac = lane & 3;

    // producer: 2 float4 jobs per thread (32 k-rows x 32 cols)
    const int kl0 = tid >> 5;           // 0..15
    const int kl1 = kl0 + 16;           // 16..31
    const int col = lane;               // 0..31
    const int hw  = hw0 + col * 4;
    const bool ok = hw < HW;

    float acc[4][4][4];
#pragma unroll
    for (int i = 0; i < 4; ++i)
#pragma unroll
        for (int j = 0; j < 4; ++j)
#pragma unroll
            for (int k = 0; k < 4; ++k) acc[i][j][k] = 0.f;

    auto tapRange = [&](int ci, int& lo, int& hi) {
        int g  = ci >> 6;
        int cg = ci & 63;
        if (g == 0 || cg >= 32) { lo = 0;  hi = 0;  }
        else if (cg < 16)       { lo = -g; hi = -1; }
        else                    { lo = 1;  hi = g;  }
    };

    auto issueW = [&](int kt, unsigned wOff) {
#pragma unroll
        for (int j = 0; j < 4; ++j) {
            int cidx = tid + NTHREADS * j;      // 16B chunk id, 2048 total
            int row  = cidx >> 3;
            int colf = (cidx & 7) * 4;
            cp_async16(sb + wOff + (row * WSTRIDE + colf) * 4,
                       net_w + (size_t)row * C + kt * BK + colf);
        }
        asm volatile("cp.async.commit_group;\n" ::: "memory");
    };

    // raw tap loads for one k-row into register buffer (no adds)
    auto issueRow = [&](int kt, int kl, float4 xv[3]) {
        int ci = kt * BK + kl;
        int lo, hi;
        tapRange(ci, lo, hi);
        int ntap = hi - lo + 1;
#pragma unroll
        for (int i = 0; i < 3; ++i) {
            xv[i] = make_float4(0.f, 0.f, 0.f, 0.f);
            if (i < ntap) {
                int dt = lo + i;
                int tt = t + dt;
                if (ok && (unsigned)tt < 8u)
                    xv[i] = *reinterpret_cast<const float4*>(
                        x + ((size_t)(z + dt) * C + ci) * HW + hw);
            }
        }
    };

    auto finishRow = [&](unsigned yOff, int kl, const float4 xv[3]) {
        float4 v;
        v.x = xv[0].x + xv[1].x + xv[2].x;
        v.y = xv[0].y + xv[1].y + xv[2].y;
        v.z = xv[0].z + xv[1].z + xv[2].z;
        v.w = xv[0].w + xv[1].w + xv[2].w;
        uint4 s;
        s.x = f2tf32(v.x); s.y = f2tf32(v.y);
        s.z = f2tf32(v.z); s.w = f2tf32(v.w);
        *reinterpret_cast<uint4*>(smem + yOff + (kl * YSTRIDE + col * 4) * 4) = s;
    };

    // ---- prologue: fill buffer 0 ----
    {
        float4 xa[3], xb[3];
        issueW(0, 0);
        issueRow(0, kl0, xa);
        issueRow(0, kl1, xb);
        finishRow(WBYTES, kl0, xa);
        finishRow(WBYTES, kl1, xb);
        asm volatile("cp.async.wait_group 0;\n" ::: "memory");
        __syncthreads();
    }

    float4 xa[3], xb[3];
    for (int kt = 0; kt < KTILES; ++kt) {
        const int cur = kt & 1;
        const unsigned wCur = cur ? STAGEB : 0;
        const unsigned yCur = wCur + WBYTES;
        const unsigned wNxt = cur ? 0 : STAGEB;
        const unsigned yNxt = wNxt + WBYTES;

        if (kt < KTILES - 1) {
            issueW(kt + 1, wNxt);       // async into next W buffer
            issueRow(kt + 1, kl0, xa);  // raw LDGs in flight across the MMA block
            issueRow(kt + 1, kl1, xb);
        }

        const unsigned* Ws = reinterpret_cast<const unsigned*>(smem + wCur);
        const unsigned* Ys = reinterpret_cast<const unsigned*>(smem + yCur);
#pragma unroll
        for (int kk = 0; kk < 4; ++kk) {
            int k0 = kk * 8;
            unsigned a[4][4], b[4][2];
#pragma unroll
            for (int mi = 0; mi < 4; ++mi) {
                int m = wm + mi * 16;
                a[mi][0] = Ws[(m + ar    ) * WSTRIDE + k0 + ac    ];
                a[mi][1] = Ws[(m + ar + 8) * WSTRIDE + k0 + ac    ];
                a[mi][2] = Ws[(m + ar    ) * WSTRIDE + k0 + ac + 4];
                a[mi][3] = Ws[(m + ar + 8) * WSTRIDE + k0 + ac + 4];
            }
#pragma unroll
            for (int ni = 0; ni < 4; ++ni) {
                int nn = wn + ni * 8 + ar;
                b[ni][0] = Ys[(k0 + ac    ) * YSTRIDE + nn];
                b[ni][1] = Ys[(k0 + ac + 4) * YSTRIDE + nn];
            }
#pragma unroll
            for (int mi = 0; mi < 4; ++mi)
#pragma unroll
                for (int ni = 0; ni < 4; ++ni) {
                    asm volatile(
                        "mma.sync.aligned.m16n8k8.row.col.f32.tf32.tf32.f32 "
                        "{%0,%1,%2,%3}, {%4,%5,%6,%7}, {%8,%9}, {%0,%1,%2,%3};\n"
                        : "+f"(acc[mi][ni][0]), "+f"(acc[mi][ni][1]),
                          "+f"(acc[mi][ni][2]), "+f"(acc[mi][ni][3])
                        : "r"(a[mi][0]), "r"(a[mi][1]),
                          "r"(a[mi][2]), "r"(a[mi][3]),
                          "r"(b[ni][0]), "r"(b[ni][1]));
                }
        }

        if (kt < KTILES - 1) {
            finishRow(yNxt, kl0, xa);   // loads landed during MMA block
            finishRow(yNxt, kl1, xb);
            asm volatile("cp.async.wait_group 0;\n" ::: "memory");
            __syncthreads();
        }
    }

    // ---- epilogue ----
    const int r  = lane >> 2;
    const int c2 = (lane & 3) * 2;
#pragma unroll
    for (int mi = 0; mi < 4; ++mi) {
#pragma unroll
        for (int ni = 0; ni < 4; ++ni) {
            int co  = wm + mi * 16 + r;
            int hwo = hw0 + wn + ni * 8 + c2;
            if (hwo < HW) {
                float2 v0 = make_float2(acc[mi][ni][0], acc[mi][ni][1]);
                float2 v1 = make_float2(acc[mi][ni][2], acc[mi][ni][3]);
                *reinterpret_cast<float2*>(
                    out + ((size_t)z * C + co) * HW + hwo) = v0;
                *reinterpret_cast<float2*>(
                    out + ((size_t)z * C + co + 8) * HW + hwo) = v1;
            }
        }
    }
}

extern "C" void kernel_launch(void* const* d_in, const int* in_sizes, int n_in,
                              void* d_out, int out_size) {
    const float* x     = (const float*)d_in[0];
    const float* net_w = (const float*)d_in[5];
    float* out = (float*)d_out;

    static bool attr_done = false;
    if (!attr_done) {
        cudaFuncSetAttribute(msconv_kernel,
                             cudaFuncAttributeMaxDynamicSharedMemorySize,
                             SMEM_BYTES);
        attr_done = true;
    }

    dim3 grid(NT, (HW + BN - 1) / BN);   // 64 x 25 = 1600 CTAs, z fastest
    msconv_kernel<<<grid, NTHREADS, SMEM_BYTES>>>(x, net_w, out);
}